// round 11
// baseline (speedup 1.0000x reference)
#include <cuda_runtime.h>
#include <cuda_fp16.h>
#include <math.h>

// ---------------- problem constants (fixed-shape problem) ----------------
#define NN 100000
#define EE 3200000
#define F_IN 128
#define HID 64
#define NLAYER 64
#define NCLASS 47
#define ALPHA 0.1f
#define THETA 0.5f

// ---------------- scratch (static device globals; no allocation) ---------
// Feature buffers hold PRE-SCALED rows:  hhat = dinv[r] * h[r]  (fp16).
// Row NN is a phantom all-zero row used to pad edge-chunk tails.
__device__ __align__(16) float  g_x0[NN * HID];          // relu(x@W1+b1), fp32
__device__ __align__(16) __half g_hA[(NN + 1) * HID];    // ping
__device__ __align__(16) __half g_hB[(NN + 1) * HID];    // pong
__device__ int   g_col[EE];          // CSR column indices
__device__ int   g_rowptr[NN + 1];
__device__ int   g_cnt[NN];          // zero at load; self-cleaned each run
__device__ int   g_cursor[NN];
__device__ float g_dinv[NN];         // 1/sqrt(deg+1)
__device__ float g_rdinv[NN];        // sqrt(deg+1)
__device__ int   g_bsum[128];
__device__ int   g_is64;

__device__ __forceinline__ const __half* pick_half(int s) {
    return (s == 1) ? g_hA : g_hB;
}
__device__ __forceinline__ __half* pick_half_mut(int s) {
    return (s == 1) ? g_hA : g_hB;
}

// packed f32x2 fma: d = a*b + d
__device__ __forceinline__ void fma2(unsigned long long& d,
                                     unsigned long long a,
                                     unsigned long long b) {
    asm("fma.rn.f32x2 %0, %1, %2, %0;" : "+l"(d) : "l"(a), "l"(b));
}

__device__ __forceinline__ int edge_at(const void* eiv, size_t idx, int is64) {
    if (is64) return (int)((const long long*)eiv)[idx];
    return ((const int*)eiv)[idx];
}

// ---------------- x0 = relu(x @ W1 + b1)  (+ inline edge-dtype detect) ----
__global__ void __launch_bounds__(256) x0_kernel(const float* __restrict__ x,
                                                 const float* __restrict__ W1,
                                                 const float* __restrict__ b1,
                                                 const unsigned int* __restrict__ eip) {
    if (blockIdx.x == 0 && threadIdx.x == 0) {
        int all0 = 1;
        for (int i = 0; i < 64; i++) {
            if (eip[2 * i + 1] != 0u) { all0 = 0; break; }
        }
        g_is64 = all0;
    }

    __shared__ __align__(16) float Ws[F_IN * HID];  // 32KB
    int tid = threadIdx.x;
    const float4* W4 = (const float4*)W1;
    float4* Ws4 = (float4*)Ws;
#pragma unroll
    for (int i = tid; i < (F_IN * HID) / 4; i += 256) Ws4[i] = W4[i];
    __syncthreads();

    int base = blockIdx.x * 64;
    int w = tid >> 5, lane = tid & 31;
    float bx = b1[2 * lane], by = b1[2 * lane + 1];
#pragma unroll 1
    for (int i = 0; i < 8; i++) {
        int r = base + w * 8 + i;
        if (r >= NN) continue;
        float ax = bx, ay = by;
        const float4* xr = (const float4*)(x + (size_t)r * F_IN);
#pragma unroll 8
        for (int kk = 0; kk < F_IN / 4; kk++) {
            float4 xv = xr[kk];
            int k = kk * 4;
            float2 w0 = ((const float2*)(Ws + (k + 0) * HID))[lane];
            float2 w1 = ((const float2*)(Ws + (k + 1) * HID))[lane];
            float2 w2 = ((const float2*)(Ws + (k + 2) * HID))[lane];
            float2 w3 = ((const float2*)(Ws + (k + 3) * HID))[lane];
            ax += xv.x * w0.x; ay += xv.x * w0.y;
            ax += xv.y * w1.x; ay += xv.y * w1.y;
            ax += xv.z * w2.x; ay += xv.z * w2.y;
            ax += xv.w * w3.x; ay += xv.w * w3.y;
        }
        float vx = fmaxf(ax, 0.f), vy = fmaxf(ay, 0.f);
        ((float2*)(g_x0 + (size_t)r * HID))[lane] = make_float2(vx, vy);
    }
}

// ---------------- CSR: count ----------------
__global__ void count_kernel(const void* __restrict__ eiv) {
    int i = blockIdx.x * blockDim.x + threadIdx.x;
    int is64 = g_is64;
    if (i < EE) {
        int dst = edge_at(eiv, (size_t)EE + i, is64);
        atomicAdd(&g_cnt[dst], 1);
    }
}

// ---------------- CSR: block-local exclusive scan (1024 per block) -------
__global__ void scan1_kernel() {
    __shared__ int sh[256];
    int t = threadIdx.x, b = blockIdx.x;
    int base = b * 1024 + t * 4;
    int v0 = (base + 0 < NN) ? g_cnt[base + 0] : 0;
    int v1 = (base + 1 < NN) ? g_cnt[base + 1] : 0;
    int v2 = (base + 2 < NN) ? g_cnt[base + 2] : 0;
    int v3 = (base + 3 < NN) ? g_cnt[base + 3] : 0;
    int s0 = v0, s1 = s0 + v1, s2 = s1 + v2, s3 = s2 + v3;
    sh[t] = s3;
    __syncthreads();
    for (int off = 1; off < 256; off <<= 1) {
        int v = (t >= off) ? sh[t - off] : 0;
        __syncthreads();
        sh[t] += v;
        __syncthreads();
    }
    int excl = sh[t] - s3;
    if (base + 0 < NN) g_rowptr[base + 0] = excl;
    if (base + 1 < NN) g_rowptr[base + 1] = excl + s0;
    if (base + 2 < NN) g_rowptr[base + 2] = excl + s1;
    if (base + 3 < NN) g_rowptr[base + 3] = excl + s2;
    if (t == 255) g_bsum[b] = sh[255];
}

// ---------------- CSR: finalize (inline bsum prefix) + dinv + seed hA ----
__global__ void __launch_bounds__(256) scan3_kernel() {
    __shared__ int pre_sh;
    int t = threadIdx.x, b = blockIdx.x;
    if (t == 0) {
        int nb = b >> 2;
        int run = 0;
        for (int j = 0; j < nb; j++) run += g_bsum[j];
        pre_sh = run;
    }
    __syncthreads();
    int i = b * 256 + t;
    if (i < NN) {
        int rp = g_rowptr[i] + pre_sh;
        g_rowptr[i] = rp;
        g_cursor[i] = rp;
        int deg = g_cnt[i] + 1;
        float di = rsqrtf((float)deg);
        g_dinv[i] = di;
        g_rdinv[i] = sqrtf((float)deg);
        g_cnt[i] = 0;
        const float2* xr = (const float2*)(g_x0 + (size_t)i * HID);
        __half2* hw = (__half2*)(g_hA + (size_t)i * HID);
#pragma unroll
        for (int k = 0; k < 32; k++) {
            float2 v = xr[k];
            hw[k] = __floats2half2_rn(di * v.x, di * v.y);
        }
    }
    if (i == 0) g_rowptr[NN] = EE;
    if (b == 0 && t < 64) {
        g_hA[(size_t)NN * HID + t] = __float2half(0.f);
        g_hB[(size_t)NN * HID + t] = __float2half(0.f);
    }
}

// ---------------- CSR: scatter ----------------
__global__ void scatter_kernel(const void* __restrict__ eiv) {
    int i = blockIdx.x * blockDim.x + threadIdx.x;
    int is64 = g_is64;
    if (i < EE) {
        int src = edge_at(eiv, (size_t)i, is64);
        int dst = edge_at(eiv, (size_t)EE + i, is64);
        int pos = atomicAdd(&g_cursor[dst], 1);
        g_col[pos] = src;
    }
}

// ---------------- fused layer --------------------------------------------
// phase 1: p[r] = dinv[r] * (sum_edges hhat[c] + hhat[r])   (pure sum)
//          s    = (1-a)*p + a*x0
// phase 2: h = relu((1-b)s + b*(s@W));  store hhat = dinv[r]*h as fp16
__global__ void __launch_bounds__(256) layer_kernel(const float* __restrict__ Wl,
                                                    float beta, int sel_in, int sel_out) {
    __shared__ __align__(16) float Ws[HID * HID];    // 16KB
    __shared__ __align__(16) float ss[64 * 65];      // 16.6KB, pitch 65
    const __half* __restrict__ hin = pick_half(sel_in);
    __half* __restrict__ hout = pick_half_mut(sel_out);

    int tid = threadIdx.x;
    {   // stage Wl
        const float4* W4 = (const float4*)Wl;
        float4* Ws4 = (float4*)Ws;
#pragma unroll
        for (int i = tid; i < (HID * HID) / 4; i += 256) Ws4[i] = W4[i];
    }

    int base = blockIdx.x * 64;
    int w = tid >> 5, lane = tid & 31;
    int g = lane >> 4;          // edge parity group (0/1)
    int t = lane & 15;          // feature slot: features 4t..4t+3
    const unsigned FULL = 0xffffffffu;

    // warp-wide rowptr preload: lanes 0..8 hold rowptr[base+w*8 .. +8]
    int rp_lane = 0;
    {
        int idx = base + w * 8 + lane;
        if (idx > NN) idx = NN;
        if (lane < 9) rp_lane = g_rowptr[idx];
    }

    // -------- phase 1: warp-per-row gather, pipelined ACROSS rows --------
    // Row i+1's first 32-col chunk is prefetched while row i is consumed,
    // hiding the col->shfl->h startup chain. Within a chunk: 4-pair groups
    // (2 edges per LDG.64), double-buffered (R9 structure), fp32 accumulate.
    int e_cur  = __shfl_sync(FULL, rp_lane, 0);
    int e1_cur = __shfl_sync(FULL, rp_lane, 1);
    int cw_cur = NN;
    {
        int rem = e1_cur - e_cur;
        if (lane < rem) cw_cur = g_col[e_cur + lane];
    }
#pragma unroll 1
    for (int i = 0; i < 8; i++) {
        int rl = w * 8 + i;
        int r = base + rl;
        // prefetch next row's first col chunk (warp-convergent)
        int e_nxt = 0, e1_nxt = 0, cw_nxt = NN;
        if (i < 7) {
            e_nxt  = __shfl_sync(FULL, rp_lane, i + 1);
            e1_nxt = __shfl_sync(FULL, rp_lane, i + 2);
            int remn = e1_nxt - e_nxt;
            if (lane < remn) cw_nxt = g_col[e_nxt + lane];
        }
        if (r < NN) {   // warp-uniform branch (whole warp shares row r)
            float a0 = 0.f, a1 = 0.f, a2 = 0.f, a3 = 0.f;
            int e = e_cur;
            const int e1v = e1_cur;
            int cw = cw_cur;
#pragma unroll 1
            while (e < e1v) {
                int rem = e1v - e;
                int np = rem < 32 ? rem : 32;
                int nsub = (np + 7) >> 3;

                uint2 ha[4];
#pragma unroll
                for (int q = 0; q < 4; q++) {
                    int idx = 2 * q + g;
                    int c = __shfl_sync(FULL, cw, idx);
                    if (idx >= np) c = NN;
                    ha[q] = ((const uint2*)(hin + (size_t)c * HID))[t];
                }
#pragma unroll 1
                for (int s = 1; s < nsub; s++) {
                    uint2 hb[4];
#pragma unroll
                    for (int q = 0; q < 4; q++) {
                        int idx = 8 * s + 2 * q + g;
                        int c = __shfl_sync(FULL, cw, idx);
                        if (idx >= np) c = NN;
                        hb[q] = ((const uint2*)(hin + (size_t)c * HID))[t];
                    }
#pragma unroll
                    for (int q = 0; q < 4; q++) {
                        float2 f0 = __half22float2(*(__half2*)&ha[q].x);
                        float2 f1 = __half22float2(*(__half2*)&ha[q].y);
                        a0 += f0.x; a1 += f0.y; a2 += f1.x; a3 += f1.y;
                        ha[q] = hb[q];
                    }
                }
#pragma unroll
                for (int q = 0; q < 4; q++) {
                    float2 f0 = __half22float2(*(__half2*)&ha[q].x);
                    float2 f1 = __half22float2(*(__half2*)&ha[q].y);
                    a0 += f0.x; a1 += f0.y; a2 += f1.x; a3 += f1.y;
                }
                e += 32;
                if (e < e1v) {   // inline col load for extra chunks (deg > 32)
                    int rem2 = e1v - e;
                    cw = (lane < rem2) ? g_col[e + lane] : NN;
                }
            }
            // combine the two 16-lane halves
            a0 += __shfl_xor_sync(FULL, a0, 16);
            a1 += __shfl_xor_sync(FULL, a1, 16);
            a2 += __shfl_xor_sync(FULL, a2, 16);
            a3 += __shfl_xor_sync(FULL, a3, 16);
            // self loop: + hhat[r], then scale by dinv[r]
            uint2 hs = ((const uint2*)(hin + (size_t)r * HID))[t];
            float2 s0f = __half22float2(*(__half2*)&hs.x);
            float2 s1f = __half22float2(*(__half2*)&hs.y);
            a0 += s0f.x; a1 += s0f.y; a2 += s1f.x; a3 += s1f.y;
            float dr = g_dinv[r];
            float4 x0v = ((const float4*)(g_x0 + (size_t)r * HID))[t];
            if (lane < 16) {
                int bsh = rl * 65 + 4 * t;
                ss[bsh + 0] = (1.f - ALPHA) * (dr * a0) + ALPHA * x0v.x;
                ss[bsh + 1] = (1.f - ALPHA) * (dr * a1) + ALPHA * x0v.y;
                ss[bsh + 2] = (1.f - ALPHA) * (dr * a2) + ALPHA * x0v.z;
                ss[bsh + 3] = (1.f - ALPHA) * (dr * a3) + ALPHA * x0v.w;
            }
        }
        e_cur = e_nxt; e1_cur = e1_nxt; cw_cur = cw_nxt;
    }
    __syncthreads();

    // -------- phase 2: 64x64 @ 64x64 GEMM from shared, packed f32x2 FMA ----
    int rl = tid & 63;
    int gq = tid >> 6;          // 4 groups of 16 columns
    int cbase = gq * 16;
    unsigned long long acc[8];
#pragma unroll
    for (int i = 0; i < 8; i++) acc[i] = 0ull;
#pragma unroll 8
    for (int k = 0; k < HID; k++) {
        float sk = ss[rl * 65 + k];
        unsigned long long skk;
        asm("mov.b64 %0, {%1, %2};" : "=l"(skk) : "f"(sk), "f"(sk));
        const ulonglong2* wp = (const ulonglong2*)(Ws + k * HID + cbase);  // warp-uniform
        ulonglong2 p0 = wp[0], p1 = wp[1], p2 = wp[2], p3 = wp[3];
        fma2(acc[0], p0.x, skk); fma2(acc[1], p0.y, skk);
        fma2(acc[2], p1.x, skk); fma2(acc[3], p1.y, skk);
        fma2(acc[4], p2.x, skk); fma2(acc[5], p2.y, skk);
        fma2(acc[6], p3.x, skk); fma2(acc[7], p3.y, skk);
    }
    int r = base + rl;
    if (r < NN) {
        float ob = 1.f - beta;
        float di = g_dinv[r];
        unsigned int u[8];
#pragma unroll
        for (int q = 0; q < 8; q++) {
            float lo, hi;
            asm("mov.b64 {%0, %1}, %2;" : "=f"(lo), "=f"(hi) : "l"(acc[q]));
            float v0 = fmaxf(ob * ss[rl * 65 + cbase + 2 * q + 0] + beta * lo, 0.f);
            float v1 = fmaxf(ob * ss[rl * 65 + cbase + 2 * q + 1] + beta * hi, 0.f);
            __half2 h2 = __floats2half2_rn(di * v0, di * v1);
            u[q] = *(unsigned int*)&h2;
        }
        uint4* dst = (uint4*)(hout + (size_t)r * HID + cbase);  // 32B-aligned
        dst[0] = make_uint4(u[0], u[1], u[2], u[3]);
        dst[1] = make_uint4(u[4], u[5], u[6], u[7]);
    }
}

// ---------------- logits + log_softmax ----------------
__global__ void __launch_bounds__(256) out_kernel(int sel_in,
                                                  const float* __restrict__ W2,
                                                  const float* __restrict__ b2,
                                                  float* __restrict__ out) {
    __shared__ float W2s[HID * NCLASS];
    __shared__ float b2s[NCLASS];
    __shared__ float hrow[8][HID];
    const __half* __restrict__ hin = pick_half(sel_in);

    int tid = threadIdx.x;
    for (int i = tid; i < HID * NCLASS; i += 256) W2s[i] = W2[i];
    if (tid < NCLASS) b2s[tid] = b2[tid];
    __syncthreads();

    int w = tid >> 5, lane = tid & 31;
    int r = blockIdx.x * 8 + w;
    if (r < NN) {
        float rdi = g_rdinv[r];
        hrow[w][lane] = rdi * __half2float(hin[(size_t)r * HID + lane]);
        hrow[w][lane + 32] = rdi * __half2float(hin[(size_t)r * HID + lane + 32]);
    }
    __syncwarp();
    if (r >= NN) return;

    int j0 = lane, j1 = lane + 32;
    bool has1 = (j1 < NCLASS);
    float a0 = b2s[j0];
    float a1 = has1 ? b2s[j1] : 0.f;
#pragma unroll 4
    for (int k = 0; k < HID; k++) {
        float hv = hrow[w][k];
        a0 += hv * W2s[k * NCLASS + j0];
        if (has1) a1 += hv * W2s[k * NCLASS + j1];
    }
    float m = a0;
    if (has1) m = fmaxf(m, a1);
#pragma unroll
    for (int off = 16; off; off >>= 1) m = fmaxf(m, __shfl_xor_sync(0xffffffffu, m, off));
    float s = expf(a0 - m) + (has1 ? expf(a1 - m) : 0.f);
#pragma unroll
    for (int off = 16; off; off >>= 1) s += __shfl_xor_sync(0xffffffffu, s, off);
    float lse = m + logf(s);
    out[(size_t)r * NCLASS + j0] = a0 - lse;
    if (has1) out[(size_t)r * NCLASS + j1] = a1 - lse;
}

// ---------------- launch ----------------
extern "C" void kernel_launch(void* const* d_in, const int* in_sizes, int n_in,
                              void* d_out, int out_size) {
    const float* x = (const float*)d_in[0];
    const void* ei = (const void*)d_in[1];
    const float* W1 = (const float*)d_in[2];
    const float* b1 = (const float*)d_in[3];
    const float* convW = (const float*)d_in[4];
    const float* W2 = (const float*)d_in[5];
    const float* b2 = (const float*)d_in[6];
    float* out = (float*)d_out;

    const int TB = 256;
    const int nblkN = (NN + TB - 1) / TB;      // 391
    const int nblkE = (EE + TB - 1) / TB;
    const int nscan = (NN + 1023) / 1024;      // 98
    const int nrowblk = (NN + 63) / 64;        // 1563

    x0_kernel<<<nrowblk, TB>>>(x, W1, b1, (const unsigned int*)ei);
    count_kernel<<<nblkE, TB>>>(ei);
    scan1_kernel<<<nscan, TB>>>();
    scan3_kernel<<<nblkN, TB>>>();
    scatter_kernel<<<nblkE, TB>>>(ei);

    int sel_in = 1;
    for (int l = 0; l < NLAYER; l++) {
        float beta = logf(THETA / (float)(l + 1) + 1.0f);
        int sel_out = 3 - sel_in;
        layer_kernel<<<nrowblk, TB>>>(convW + (size_t)l * HID * HID, beta, sel_in, sel_out);
        sel_in = sel_out;
    }

    out_kernel<<<(NN + 7) / 8, TB>>>(sel_in, W2, b2, out);
}

// round 12
// speedup vs baseline: 1.1185x; 1.1185x over previous
#include <cuda_runtime.h>
#include <cuda_fp16.h>
#include <math.h>

// ---------------- problem constants (fixed-shape problem) ----------------
#define NN 100000
#define EE 3200000
#define F_IN 128
#define HID 64
#define NLAYER 64
#define NCLASS 47
#define ALPHA 0.1f
#define THETA 0.5f
#define SF 32.0f          // fp8 storage scale (keeps values in e4m3 normal range)
#define SFI (1.0f / 32.0f)

// ---------------- scratch (static device globals; no allocation) ---------
// Feature buffers hold PRE-SCALED rows: q = SF * dinv[r] * h[r], e4m3 fp8.
// Row NN is a phantom all-zero row used to pad edge-chunk tails.
__device__ __align__(16) float         g_x0[NN * HID];           // fp32 residual
__device__ __align__(16) unsigned char g_h8A[(NN + 1) * HID];    // ping (fp8)
__device__ __align__(16) unsigned char g_h8B[(NN + 1) * HID];    // pong (fp8)
__device__ int   g_col[EE];          // CSR column indices
__device__ int   g_rowptr[NN + 1];
__device__ int   g_cnt[NN];          // zero at load; self-cleaned each run
__device__ int   g_cursor[NN];
__device__ float g_dinv[NN];         // 1/sqrt(deg+1)
__device__ float g_rdinv[NN];        // sqrt(deg+1)
__device__ int   g_bsum[128];
__device__ int   g_is64;

__device__ __forceinline__ const unsigned char* pick8(int s) {
    return (s == 1) ? g_h8A : g_h8B;
}
__device__ __forceinline__ unsigned char* pick8_mut(int s) {
    return (s == 1) ? g_h8A : g_h8B;
}

// packed f32x2 fma: d = a*b + d
__device__ __forceinline__ void fma2(unsigned long long& d,
                                     unsigned long long a,
                                     unsigned long long b) {
    asm("fma.rn.f32x2 %0, %1, %2, %0;" : "+l"(d) : "l"(a), "l"(b));
}

// decode 4 packed e4m3 -> two float2 (features in byte order)
__device__ __forceinline__ void dec4(unsigned int u, float2& f0, float2& f1) {
    unsigned int a, b;
    asm("{\n\t"
        ".reg .b16 lo, hi;\n\t"
        "mov.b32 {lo, hi}, %2;\n\t"
        "cvt.rn.f16x2.e4m3x2 %0, lo;\n\t"
        "cvt.rn.f16x2.e4m3x2 %1, hi;\n\t"
        "}" : "=r"(a), "=r"(b) : "r"(u));
    f0 = __half22float2(*(__half2*)&a);
    f1 = __half22float2(*(__half2*)&b);
}

// encode two floats -> 2 packed e4m3 (hi -> upper byte)
__device__ __forceinline__ unsigned short enc2(float hi, float lo) {
    unsigned short p;
    asm("cvt.rn.satfinite.e4m3x2.f32 %0, %1, %2;" : "=h"(p) : "f"(hi), "f"(lo));
    return p;
}

__device__ __forceinline__ int edge_at(const void* eiv, size_t idx, int is64) {
    if (is64) return (int)((const long long*)eiv)[idx];
    return ((const int*)eiv)[idx];
}

// ---------------- x0 = relu(x @ W1 + b1)  (+ inline edge-dtype detect) ----
__global__ void __launch_bounds__(256) x0_kernel(const float* __restrict__ x,
                                                 const float* __restrict__ W1,
                                                 const float* __restrict__ b1,
                                                 const unsigned int* __restrict__ eip) {
    if (blockIdx.x == 0 && threadIdx.x == 0) {
        int all0 = 1;
        for (int i = 0; i < 64; i++) {
            if (eip[2 * i + 1] != 0u) { all0 = 0; break; }
        }
        g_is64 = all0;
    }

    __shared__ __align__(16) float Ws[F_IN * HID];  // 32KB
    int tid = threadIdx.x;
    const float4* W4 = (const float4*)W1;
    float4* Ws4 = (float4*)Ws;
#pragma unroll
    for (int i = tid; i < (F_IN * HID) / 4; i += 256) Ws4[i] = W4[i];
    __syncthreads();

    int base = blockIdx.x * 64;
    int w = tid >> 5, lane = tid & 31;
    float bx = b1[2 * lane], by = b1[2 * lane + 1];
#pragma unroll 1
    for (int i = 0; i < 8; i++) {
        int r = base + w * 8 + i;
        if (r >= NN) continue;
        float ax = bx, ay = by;
        const float4* xr = (const float4*)(x + (size_t)r * F_IN);
#pragma unroll 8
        for (int kk = 0; kk < F_IN / 4; kk++) {
            float4 xv = xr[kk];
            int k = kk * 4;
            float2 w0 = ((const float2*)(Ws + (k + 0) * HID))[lane];
            float2 w1 = ((const float2*)(Ws + (k + 1) * HID))[lane];
            float2 w2 = ((const float2*)(Ws + (k + 2) * HID))[lane];
            float2 w3 = ((const float2*)(Ws + (k + 3) * HID))[lane];
            ax += xv.x * w0.x; ay += xv.x * w0.y;
            ax += xv.y * w1.x; ay += xv.y * w1.y;
            ax += xv.z * w2.x; ay += xv.z * w2.y;
            ax += xv.w * w3.x; ay += xv.w * w3.y;
        }
        float vx = fmaxf(ax, 0.f), vy = fmaxf(ay, 0.f);
        ((float2*)(g_x0 + (size_t)r * HID))[lane] = make_float2(vx, vy);
    }
}

// ---------------- CSR: count ----------------
__global__ void count_kernel(const void* __restrict__ eiv) {
    int i = blockIdx.x * blockDim.x + threadIdx.x;
    int is64 = g_is64;
    if (i < EE) {
        int dst = edge_at(eiv, (size_t)EE + i, is64);
        atomicAdd(&g_cnt[dst], 1);
    }
}

// ---------------- CSR: block-local exclusive scan (1024 per block) -------
__global__ void scan1_kernel() {
    __shared__ int sh[256];
    int t = threadIdx.x, b = blockIdx.x;
    int base = b * 1024 + t * 4;
    int v0 = (base + 0 < NN) ? g_cnt[base + 0] : 0;
    int v1 = (base + 1 < NN) ? g_cnt[base + 1] : 0;
    int v2 = (base + 2 < NN) ? g_cnt[base + 2] : 0;
    int v3 = (base + 3 < NN) ? g_cnt[base + 3] : 0;
    int s0 = v0, s1 = s0 + v1, s2 = s1 + v2, s3 = s2 + v3;
    sh[t] = s3;
    __syncthreads();
    for (int off = 1; off < 256; off <<= 1) {
        int v = (t >= off) ? sh[t - off] : 0;
        __syncthreads();
        sh[t] += v;
        __syncthreads();
    }
    int excl = sh[t] - s3;
    if (base + 0 < NN) g_rowptr[base + 0] = excl;
    if (base + 1 < NN) g_rowptr[base + 1] = excl + s0;
    if (base + 2 < NN) g_rowptr[base + 2] = excl + s1;
    if (base + 3 < NN) g_rowptr[base + 3] = excl + s2;
    if (t == 255) g_bsum[b] = sh[255];
}

// ---------------- CSR: finalize (inline bsum prefix) + dinv + seed h8A ---
__global__ void __launch_bounds__(256) scan3_kernel() {
    __shared__ int pre_sh;
    int t = threadIdx.x, b = blockIdx.x;
    if (t == 0) {
        int nb = b >> 2;
        int run = 0;
        for (int j = 0; j < nb; j++) run += g_bsum[j];
        pre_sh = run;
    }
    __syncthreads();
    int i = b * 256 + t;
    if (i < NN) {
        int rp = g_rowptr[i] + pre_sh;
        g_rowptr[i] = rp;
        g_cursor[i] = rp;
        int deg = g_cnt[i] + 1;
        float di = rsqrtf((float)deg);
        g_dinv[i] = di;
        g_rdinv[i] = sqrtf((float)deg);
        g_cnt[i] = 0;
        // seed h8A with q0 = SF * dinv * x0 (fp8 e4m3)
        float s = SF * di;
        const float4* xr = (const float4*)(g_x0 + (size_t)i * HID);
        unsigned int* hw = (unsigned int*)(g_h8A + (size_t)i * HID);
#pragma unroll
        for (int k = 0; k < 16; k++) {
            float4 v = xr[k];
            unsigned short lo = enc2(s * v.y, s * v.x);
            unsigned short hi = enc2(s * v.w, s * v.z);
            hw[k] = ((unsigned int)hi << 16) | lo;
        }
    }
    if (i == 0) g_rowptr[NN] = EE;
    if (b == 0 && t < 16) {       // phantom row NN = 0 in both buffers
        ((unsigned int*)(g_h8A + (size_t)NN * HID))[t] = 0u;
        ((unsigned int*)(g_h8B + (size_t)NN * HID))[t] = 0u;
    }
}

// ---------------- CSR: scatter ----------------
__global__ void scatter_kernel(const void* __restrict__ eiv) {
    int i = blockIdx.x * blockDim.x + threadIdx.x;
    int is64 = g_is64;
    if (i < EE) {
        int src = edge_at(eiv, (size_t)i, is64);
        int dst = edge_at(eiv, (size_t)EE + i, is64);
        int pos = atomicAdd(&g_cursor[dst], 1);
        g_col[pos] = src;
    }
}

// ---------------- fused layer --------------------------------------------
// phase 1: p[r] = (dinv[r]/SF) * (sum_edges q[c] + q[r])   (pure sum, fp8 rows)
//          s    = (1-a)*p + a*x0
// phase 2: h = relu((1-b)s + b*(s@W));  store q = SF*dinv[r]*h as fp8
__global__ void __launch_bounds__(256) layer_kernel(const float* __restrict__ Wl,
                                                    float beta, int sel_in, int sel_out) {
    __shared__ __align__(16) float Ws[HID * HID];    // 16KB
    __shared__ __align__(16) float ss[64 * 65];      // 16.6KB, pitch 65
    const unsigned char* __restrict__ hin = pick8(sel_in);
    unsigned char* __restrict__ hout = pick8_mut(sel_out);

    int tid = threadIdx.x;
    {   // stage Wl
        const float4* W4 = (const float4*)Wl;
        float4* Ws4 = (float4*)Ws;
#pragma unroll
        for (int i = tid; i < (HID * HID) / 4; i += 256) Ws4[i] = W4[i];
    }

    int base = blockIdx.x * 64;
    int w = tid >> 5, lane = tid & 31;
    int g = lane >> 4;          // edge parity group (0/1)
    int t = lane & 15;          // feature slot: features 4t..4t+3 (4 fp8 = uint)
    const unsigned FULL = 0xffffffffu;

    // -------- phase 1: warp-per-row unweighted gather (R9 structure) ------
    // 32 cols coalesced per chunk; 8-edge subchunks (4 pairs, 2 edges per
    // LDG.32), double-buffered; fp32 accumulate. Tail lanes -> phantom row.
#pragma unroll 1
    for (int i = 0; i < 8; i++) {
        int rl = w * 8 + i;
        int r = base + rl;
        if (r < NN) {
            float a0 = 0.f, a1 = 0.f, a2 = 0.f, a3 = 0.f;
            int e = g_rowptr[r];
            const int e1 = g_rowptr[r + 1];
#pragma unroll 1
            while (e < e1) {
                int rem = e1 - e;
                int cw = (lane < rem) ? g_col[e + lane] : NN;
                int np = rem < 32 ? rem : 32;
                int nsub = (np + 7) >> 3;

                unsigned int ha[4];
#pragma unroll
                for (int q = 0; q < 4; q++) {
                    int idx = 2 * q + g;
                    int c = __shfl_sync(FULL, cw, idx);
                    if (idx >= np) c = NN;
                    ha[q] = ((const unsigned int*)(hin + (size_t)c * HID))[t];
                }
#pragma unroll 1
                for (int s = 1; s < nsub; s++) {
                    unsigned int hb[4];
#pragma unroll
                    for (int q = 0; q < 4; q++) {
                        int idx = 8 * s + 2 * q + g;
                        int c = __shfl_sync(FULL, cw, idx);
                        if (idx >= np) c = NN;
                        hb[q] = ((const unsigned int*)(hin + (size_t)c * HID))[t];
                    }
#pragma unroll
                    for (int q = 0; q < 4; q++) {
                        float2 f0, f1;
                        dec4(ha[q], f0, f1);
                        a0 += f0.x; a1 += f0.y; a2 += f1.x; a3 += f1.y;
                        ha[q] = hb[q];
                    }
                }
#pragma unroll
                for (int q = 0; q < 4; q++) {
                    float2 f0, f1;
                    dec4(ha[q], f0, f1);
                    a0 += f0.x; a1 += f0.y; a2 += f1.x; a3 += f1.y;
                }
                e += 32;
            }
            // combine the two 16-lane halves
            a0 += __shfl_xor_sync(FULL, a0, 16);
            a1 += __shfl_xor_sync(FULL, a1, 16);
            a2 += __shfl_xor_sync(FULL, a2, 16);
            a3 += __shfl_xor_sync(FULL, a3, 16);
            // self loop: + q[r], then scale by dinv[r]/SF
            {
                unsigned int hs = ((const unsigned int*)(hin + (size_t)r * HID))[t];
                float2 f0, f1;
                dec4(hs, f0, f1);
                a0 += f0.x; a1 += f0.y; a2 += f1.x; a3 += f1.y;
            }
            float drs = g_dinv[r] * SFI;
            float4 x0v = ((const float4*)(g_x0 + (size_t)r * HID))[t];
            if (lane < 16) {
                int bsh = rl * 65 + 4 * t;
                ss[bsh + 0] = (1.f - ALPHA) * (drs * a0) + ALPHA * x0v.x;
                ss[bsh + 1] = (1.f - ALPHA) * (drs * a1) + ALPHA * x0v.y;
                ss[bsh + 2] = (1.f - ALPHA) * (drs * a2) + ALPHA * x0v.z;
                ss[bsh + 3] = (1.f - ALPHA) * (drs * a3) + ALPHA * x0v.w;
            }
        }
    }
    __syncthreads();

    // -------- phase 2: 64x64 @ 64x64 GEMM from shared, packed f32x2 FMA ----
    int rl = tid & 63;
    int gq = tid >> 6;          // 4 groups of 16 columns
    int cbase = gq * 16;
    unsigned long long acc[8];
#pragma unroll
    for (int i = 0; i < 8; i++) acc[i] = 0ull;
#pragma unroll 8
    for (int k = 0; k < HID; k++) {
        float sk = ss[rl * 65 + k];
        unsigned long long skk;
        asm("mov.b64 %0, {%1, %2};" : "=l"(skk) : "f"(sk), "f"(sk));
        const ulonglong2* wp = (const ulonglong2*)(Ws + k * HID + cbase);  // warp-uniform
        ulonglong2 p0 = wp[0], p1 = wp[1], p2 = wp[2], p3 = wp[3];
        fma2(acc[0], p0.x, skk); fma2(acc[1], p0.y, skk);
        fma2(acc[2], p1.x, skk); fma2(acc[3], p1.y, skk);
        fma2(acc[4], p2.x, skk); fma2(acc[5], p2.y, skk);
        fma2(acc[6], p3.x, skk); fma2(acc[7], p3.y, skk);
    }
    int r = base + rl;
    if (r < NN) {
        float ob = 1.f - beta;
        float sc = SF * g_dinv[r];
        unsigned short u16[8];
#pragma unroll
        for (int q = 0; q < 8; q++) {
            float lo, hi;
            asm("mov.b64 {%0, %1}, %2;" : "=f"(lo), "=f"(hi) : "l"(acc[q]));
            float v0 = fmaxf(ob * ss[rl * 65 + cbase + 2 * q + 0] + beta * lo, 0.f);
            float v1 = fmaxf(ob * ss[rl * 65 + cbase + 2 * q + 1] + beta * hi, 0.f);
            u16[q] = enc2(sc * v1, sc * v0);
        }
        unsigned int p0 = ((unsigned int)u16[1] << 16) | u16[0];
        unsigned int p1 = ((unsigned int)u16[3] << 16) | u16[2];
        unsigned int p2 = ((unsigned int)u16[5] << 16) | u16[4];
        unsigned int p3 = ((unsigned int)u16[7] << 16) | u16[6];
        *(uint4*)(hout + (size_t)r * HID + cbase) = make_uint4(p0, p1, p2, p3);
    }
}

// ---------------- logits + log_softmax ----------------
__global__ void __launch_bounds__(256) out_kernel(int sel_in,
                                                  const float* __restrict__ W2,
                                                  const float* __restrict__ b2,
                                                  float* __restrict__ out) {
    __shared__ float W2s[HID * NCLASS];
    __shared__ float b2s[NCLASS];
    __shared__ float hrow[8][HID];
    const unsigned char* __restrict__ hin = pick8(sel_in);

    int tid = threadIdx.x;
    for (int i = tid; i < HID * NCLASS; i += 256) W2s[i] = W2[i];
    if (tid < NCLASS) b2s[tid] = b2[tid];
    __syncthreads();

    int w = tid >> 5, lane = tid & 31;
    int r = blockIdx.x * 8 + w;
    if (r < NN && lane < 16) {
        float s = g_rdinv[r] * SFI;   // undo SF*dinv pre-scaling
        unsigned int u = ((const unsigned int*)(hin + (size_t)r * HID))[lane];
        float2 f0, f1;
        dec4(u, f0, f1);
        hrow[w][4 * lane + 0] = s * f0.x;
        hrow[w][4 * lane + 1] = s * f0.y;
        hrow[w][4 * lane + 2] = s * f1.x;
        hrow[w][4 * lane + 3] = s * f1.y;
    }
    __syncwarp();
    if (r >= NN) return;

    int j0 = lane, j1 = lane + 32;
    bool has1 = (j1 < NCLASS);
    float a0 = b2s[j0];
    float a1 = has1 ? b2s[j1] : 0.f;
#pragma unroll 4
    for (int k = 0; k < HID; k++) {
        float hv = hrow[w][k];
        a0 += hv * W2s[k * NCLASS + j0];
        if (has1) a1 += hv * W2s[k * NCLASS + j1];
    }
    float m = a0;
    if (has1) m = fmaxf(m, a1);
#pragma unroll
    for (int off = 16; off; off >>= 1) m = fmaxf(m, __shfl_xor_sync(0xffffffffu, m, off));
    float s = expf(a0 - m) + (has1 ? expf(a1 - m) : 0.f);
#pragma unroll
    for (int off = 16; off; off >>= 1) s += __shfl_xor_sync(0xffffffffu, s, off);
    float lse = m + logf(s);
    out[(size_t)r * NCLASS + j0] = a0 - lse;
    if (has1) out[(size_t)r * NCLASS + j1] = a1 - lse;
}

// ---------------- launch ----------------
extern "C" void kernel_launch(void* const* d_in, const int* in_sizes, int n_in,
                              void* d_out, int out_size) {
    const float* x = (const float*)d_in[0];
    const void* ei = (const void*)d_in[1];
    const float* W1 = (const float*)d_in[2];
    const float* b1 = (const float*)d_in[3];
    const float* convW = (const float*)d_in[4];
    const float* W2 = (const float*)d_in[5];
    const float* b2 = (const float*)d_in[6];
    float* out = (float*)d_out;

    const int TB = 256;
    const int nblkN = (NN + TB - 1) / TB;      // 391
    const int nblkE = (EE + TB - 1) / TB;
    const int nscan = (NN + 1023) / 1024;      // 98
    const int nrowblk = (NN + 63) / 64;        // 1563

    x0_kernel<<<nrowblk, TB>>>(x, W1, b1, (const unsigned int*)ei);
    count_kernel<<<nblkE, TB>>>(ei);
    scan1_kernel<<<nscan, TB>>>();
    scan3_kernel<<<nblkN, TB>>>();
    scatter_kernel<<<nblkE, TB>>>(ei);

    int sel_in = 1;
    for (int l = 0; l < NLAYER; l++) {
        float beta = logf(THETA / (float)(l + 1) + 1.0f);
        int sel_out = 3 - sel_in;
        layer_kernel<<<nrowblk, TB>>>(convW + (size_t)l * HID * HID, beta, sel_in, sel_out);
        sel_in = sel_out;
    }

    out_kernel<<<(NN + 7) / 8, TB>>>(sel_in, W2, b2, out);
}